// round 15
// baseline (speedup 1.0000x reference)
#include <cuda_runtime.h>
#include <cuda_fp16.h>

// WindowAttention fused, fp16 mma.sync + ldmatrix(x4 B-operands) + cp.async.
// R15: all B fragments via ldmatrix.x4 (paired 8-col slices) -> ~40% fewer LDSM.
// smem 103296 B -> 2 CTAs/SM, __launch_bounds__(512, 2).
// One CTA per window (16384), 512 threads (16 warps).
//
// SMEM:
//  XS  half[64][136]   x, later O            @ 0      (17408)
//  QS  half[64][136]   q*scale               @ 17408  (17408)
//  KS  half[56][136]   k (pad rows zeroed)   @ 34816  (15232)
//  VT  half[128][72]   V^T [dim][tok], zeroed@ 50048  (18432)
//  WT  half[128][136]  weight tile (single)  @ 68480  (34816)
// total 103296 B.

#define XS_OFF   0
#define QS_OFF   17408
#define KS_OFF   34816
#define VT_OFF   50048
#define WT_OFF   68480
#define SMEM_BYTES 103296
#define RSH 136
#define VTS 72
// KS pad rows (49..55) @ 48144, contiguous with VT -> one zero region.
#define ZERO_OFF 48144
#define ZERO_U4  1271   // (1904 + 18432) / 16

__device__ __half g_qkvw[384 * 128];
__device__ __half g_projw[128 * 128];
__device__ __half g_cbias[256 * 4 * 49 * 56];   // [wg][h][i][j-padded]

// ---------------- precompute: half weights + combined bias ------------------
__global__ void precompute_k(const float* __restrict__ mask,
                             const float* __restrict__ qkv_w,
                             const float* __restrict__ proj_w,
                             const float* __restrict__ rpb,
                             const int*   __restrict__ rpi)
{
    int blk = blockIdx.x, tid = threadIdx.x;
    if (blk < 256) {
        const float* mg = mask + (size_t)blk * 2401;
        __half* dst = g_cbias + (size_t)blk * 10976;
        for (int idx = tid; idx < 10976; idx += 256) {
            int h = idx / 2744, rem = idx - h * 2744;
            int i = rem / 56, j = rem - i * 56;
            float v = (j < 49) ? rpb[rpi[i * 49 + j] * 4 + h] + mg[i * 49 + j]
                               : -20000.0f;
            dst[idx] = __float2half_rn(v);
        }
    } else if (blk < 259) {
        int base = (blk - 256) * 16384;
        for (int idx = tid; idx < 16384; idx += 256)
            g_qkvw[base + idx] = __float2half_rn(qkv_w[base + idx]);
    } else {
        for (int idx = tid; idx < 16384; idx += 256)
            g_projw[idx] = __float2half_rn(proj_w[idx]);
    }
}

// ---------------- helpers ---------------------------------------------------
__device__ __forceinline__ void cpa16(unsigned dst, const void* src) {
    asm volatile("cp.async.cg.shared.global [%0], [%1], 16;" :: "r"(dst), "l"(src));
}
#define CPA_COMMIT() asm volatile("cp.async.commit_group;")
#define CPA_WAIT0()  asm volatile("cp.async.wait_group 0;")

__device__ __forceinline__ void ldsm4(unsigned addr, unsigned& r0, unsigned& r1,
                                      unsigned& r2, unsigned& r3) {
    asm volatile("ldmatrix.sync.aligned.m8n8.x4.shared.b16 {%0,%1,%2,%3}, [%4];"
                 : "=r"(r0), "=r"(r1), "=r"(r2), "=r"(r3) : "r"(addr));
}
__device__ __forceinline__ void ldsm2(unsigned addr, unsigned& r0, unsigned& r1) {
    asm volatile("ldmatrix.sync.aligned.m8n8.x2.shared.b16 {%0,%1}, [%2];"
                 : "=r"(r0), "=r"(r1) : "r"(addr));
}
__device__ __forceinline__ void mma16(float4& c, unsigned a0, unsigned a1, unsigned a2,
                                      unsigned a3, unsigned b0, unsigned b1) {
    asm volatile(
        "mma.sync.aligned.m16n8k16.row.col.f32.f16.f16.f32 "
        "{%0,%1,%2,%3},{%4,%5,%6,%7},{%8,%9},{%0,%1,%2,%3};"
        : "+f"(c.x), "+f"(c.y), "+f"(c.z), "+f"(c.w)
        : "r"(a0), "r"(a1), "r"(a2), "r"(a3), "r"(b0), "r"(b1));
}
__device__ __forceinline__ void st2(__half* p, float a, float b) {
    *reinterpret_cast<__half2*>(p) = __floats2half2_rn(a, b);
}
__device__ __forceinline__ unsigned pk(float a, float b) {
    __half2 h = __floats2half2_rn(a, b);
    return *reinterpret_cast<unsigned*>(&h);
}

// ---------------- main kernel ----------------------------------------------
__global__ __launch_bounds__(512, 2)
void winattn_h4(const float* __restrict__ x,
                const float* __restrict__ qkv_b,
                const float* __restrict__ proj_b,
                float* __restrict__ out)
{
    extern __shared__ __align__(16) char smb[];
    __half* xs  = reinterpret_cast<__half*>(smb + XS_OFF);
    __half* qs  = reinterpret_cast<__half*>(smb + QS_OFF);
    __half* ks  = reinterpret_cast<__half*>(smb + KS_OFF);
    __half* vt  = reinterpret_cast<__half*>(smb + VT_OFF);

    const unsigned su = (unsigned)__cvta_generic_to_shared(smb);

    const int b   = blockIdx.x;
    const int tid = threadIdx.x;
    const int w   = tid >> 5;
    const int l   = tid & 31;
    const int g   = l >> 2;
    const int t   = l & 3;
    const int t2  = 2 * t;
    const int l15 = l & 15, lhi = (l >> 4) << 3, l7 = l & 7, l8 = l & 8;
    // B-operand x4 lane mapping: slice = (l&16)>>4, row-in-pair = slice*8 + l7,
    // k-half = l&8. Covers 16 rows x 16 k per ldsm4.
    const int lrow = ((l & 16) >> 1) + l7;      // 0..15

    const float SCALE = 0.17677669529663687f;   // 32^-0.5

    // -- cp.async weight tile 0 first (max overlap with init) --
    #pragma unroll
    for (int it = 0; it < 4; it++) {
        int idx = tid + it * 512, r = idx >> 4, c = idx & 15;
        cpa16(su + WT_OFF + r * 272 + c * 16, g_qkvw + r * 128 + c * 8);
    }
    CPA_COMMIT();

    // -- x -> XS (half); zero KS pad rows + VT (contiguous) --
    {
        const float4* xg = reinterpret_cast<const float4*>(x + (size_t)b * (49 * 128));
        #pragma unroll
        for (int it = 0; it < 4; it++) {
            int idx = tid + it * 512;
            if (idx < 49 * 32) {
                int r = idx >> 5, c = idx & 31;
                float4 v = xg[idx];
                __half* p = xs + r * RSH + c * 4;
                *reinterpret_cast<__half2*>(p)     = __floats2half2_rn(v.x, v.y);
                *reinterpret_cast<__half2*>(p + 2) = __floats2half2_rn(v.z, v.w);
            }
        }
        uint4 z = make_uint4(0, 0, 0, 0);
        uint4* zp = reinterpret_cast<uint4*>(smb + ZERO_OFF);
        #pragma unroll
        for (int it = 0; it < 3; it++) {
            int idx = tid + it * 512;
            if (idx < ZERO_U4) zp[idx] = z;
        }
    }

    const int mt = w & 3, nh = w >> 2;
    const int r0 = mt * 16 + g, r1 = r0 + 8;
    const bool v0 = r0 < 49, v1 = r1 < 49;

    const unsigned xAddr = su + XS_OFF + (unsigned)((mt * 16 + l15) * RSH + lhi) * 2;
    // B x4 base for weight tiles: rows nh*32 + n8*16 + lrow, k-offset l8
    const unsigned wAddr4 = su + WT_OFF + (unsigned)(((nh * 32 + lrow) * RSH + l8) * 2);

    // ================ Phase A: QKV projection, 3 tiles (single buffer) ========
    #pragma unroll 1
    for (int wi = 0; wi < 3; wi++) {
        CPA_WAIT0();
        __syncthreads();          // tile resident + all prior smem writes visible

        float4 acc[4];
        #pragma unroll
        for (int a = 0; a < 4; a++) acc[a] = make_float4(0.f, 0.f, 0.f, 0.f);

        #pragma unroll
        for (int kss = 0; kss < 8; kss++) {
            unsigned a0, a1, a2, a3, b0, b1, b2, b3;
            ldsm4(xAddr + kss * 32, a0, a1, a2, a3);
            #pragma unroll
            for (int n8 = 0; n8 < 2; n8++) {
                ldsm4(wAddr4 + n8 * (16 * RSH * 2) + kss * 32, b0, b1, b2, b3);
                mma16(acc[2 * n8],     a0, a1, a2, a3, b0, b1);
                mma16(acc[2 * n8 + 1], a0, a1, a2, a3, b2, b3);
            }
        }
        #pragma unroll
        for (int n4 = 0; n4 < 4; n4++) {
            int d  = nh * 32 + n4 * 8 + t2;
            int d3 = wi * 128 + d;
            float bx = __ldg(qkv_b + d3), by = __ldg(qkv_b + d3 + 1);
            if (wi == 0) {
                if (v0) st2(qs + r0 * RSH + d, (acc[n4].x + bx) * SCALE, (acc[n4].y + by) * SCALE);
                if (v1) st2(qs + r1 * RSH + d, (acc[n4].z + bx) * SCALE, (acc[n4].w + by) * SCALE);
            } else if (wi == 1) {
                if (v0) st2(ks + r0 * RSH + d, acc[n4].x + bx, acc[n4].y + by);
                if (v1) st2(ks + r1 * RSH + d, acc[n4].z + bx, acc[n4].w + by);
            } else {
                if (v0) {
                    vt[d * VTS + r0]       = __float2half_rn(acc[n4].x + bx);
                    vt[(d + 1) * VTS + r0] = __float2half_rn(acc[n4].y + by);
                }
                if (v1) {
                    vt[d * VTS + r1]       = __float2half_rn(acc[n4].z + bx);
                    vt[(d + 1) * VTS + r1] = __float2half_rn(acc[n4].w + by);
                }
            }
        }
        __syncthreads();          // all warps done reading WT

        // next tile into the freed buffer: qkv tiles 1,2 then proj
        const __half* nsrc = (wi < 2) ? (g_qkvw + (wi + 1) * 16384) : g_projw;
        #pragma unroll
        for (int it = 0; it < 4; it++) {
            int idx = tid + it * 512, r = idx >> 4, c = idx & 15;
            cpa16(su + WT_OFF + r * 272 + c * 16, nsrc + r * 128 + c * 8);
        }
        CPA_COMMIT();
    }
    // after loop: QS/KS/VT visible (post-wi2 sync); proj load in flight over B+C

    // ================ Phase B: scores + bias -> register softmax ==============
    const int h = w & 3, mq = w >> 2;
    const int qr0 = mq * 16 + g, qr1 = qr0 + 8;

    unsigned pa0[4], pa1[4], pa2[4], pa3[4];    // P fragments for Phase C
    {
        const unsigned qAddr  = su + QS_OFF + (unsigned)((mq * 16 + l15) * RSH + h * 32 + lhi) * 2;
        const unsigned kAddr4 = su + KS_OFF + (unsigned)((lrow * RSH + h * 32 + l8) * 2);
        const unsigned kAddr2 = su + KS_OFF + (unsigned)(((48 + l7) * RSH + h * 32 + l8) * 2);

        // prefetch combined bias (global, L1/L2-hot) into regs
        const __half2* cb0 = reinterpret_cast<const __half2*>(
            g_cbias + (size_t)(b & 255) * 10976 + (h * 49 + min(qr0, 48)) * 56);
        const __half2* cb1 = reinterpret_cast<const __half2*>(
            g_cbias + (size_t)(b & 255) * 10976 + (h * 49 + min(qr1, 48)) * 56);
        __half2 c0[7], c1[7];
        #pragma unroll
        for (int nt = 0; nt < 7; nt++) { c0[nt] = cb0[nt * 4 + t]; c1[nt] = cb1[nt * 4 + t]; }

        float4 acc[7];
        #pragma unroll
        for (int nt = 0; nt < 7; nt++) acc[nt] = make_float4(0.f, 0.f, 0.f, 0.f);

        #pragma unroll
        for (int kss = 0; kss < 2; kss++) {
            unsigned a0, a1, a2, a3, b0, b1, b2, b3;
            ldsm4(qAddr + kss * 32, a0, a1, a2, a3);
            #pragma unroll
            for (int n8 = 0; n8 < 3; n8++) {       // slices 0..5 via x4 pairs
                ldsm4(kAddr4 + n8 * (16 * RSH * 2) + kss * 32, b0, b1, b2, b3);
                mma16(acc[2 * n8],     a0, a1, a2, a3, b0, b1);
                mma16(acc[2 * n8 + 1], a0, a1, a2, a3, b2, b3);
            }
            ldsm2(kAddr2 + kss * 32, b0, b1);       // slice 6
            mma16(acc[6], a0, a1, a2, a3, b0, b1);
        }
        float m0 = -3.0e38f, m1 = -3.0e38f;
        #pragma unroll
        for (int nt = 0; nt < 7; nt++) {
            float2 f0 = __half22float2(c0[nt]);
            float2 f1 = __half22float2(c1[nt]);
            acc[nt].x += f0.x; acc[nt].y += f0.y;
            acc[nt].z += f1.x; acc[nt].w += f1.y;
            m0 = fmaxf(m0, fmaxf(acc[nt].x, acc[nt].y));
            m1 = fmaxf(m1, fmaxf(acc[nt].z, acc[nt].w));
        }
        m0 = fmaxf(m0, __shfl_xor_sync(0xffffffffu, m0, 1));
        m0 = fmaxf(m0, __shfl_xor_sync(0xffffffffu, m0, 2));
        m1 = fmaxf(m1, __shfl_xor_sync(0xffffffffu, m1, 1));
        m1 = fmaxf(m1, __shfl_xor_sync(0xffffffffu, m1, 2));
        float s0 = 0.f, s1 = 0.f;
        #pragma unroll
        for (int nt = 0; nt < 7; nt++) {
            acc[nt].x = __expf(acc[nt].x - m0); acc[nt].y = __expf(acc[nt].y - m0);
            acc[nt].z = __expf(acc[nt].z - m1); acc[nt].w = __expf(acc[nt].w - m1);
            s0 += acc[nt].x + acc[nt].y;
            s1 += acc[nt].z + acc[nt].w;
        }
        s0 += __shfl_xor_sync(0xffffffffu, s0, 1);
        s0 += __shfl_xor_sync(0xffffffffu, s0, 2);
        s1 += __shfl_xor_sync(0xffffffffu, s1, 1);
        s1 += __shfl_xor_sync(0xffffffffu, s1, 2);
        float i0 = 1.0f / s0, i1 = 1.0f / s1;

        // pack normalized probs directly into Phase-C A-fragments
        #pragma unroll
        for (int kss = 0; kss < 3; kss++) {
            pa0[kss] = pk(acc[2 * kss].x * i0,     acc[2 * kss].y * i0);
            pa1[kss] = pk(acc[2 * kss].z * i1,     acc[2 * kss].w * i1);
            pa2[kss] = pk(acc[2 * kss + 1].x * i0, acc[2 * kss + 1].y * i0);
            pa3[kss] = pk(acc[2 * kss + 1].z * i1, acc[2 * kss + 1].w * i1);
        }
        pa0[3] = pk(acc[6].x * i0, acc[6].y * i0);   // tokens 48..55
        pa1[3] = pk(acc[6].z * i1, acc[6].w * i1);
        pa2[3] = 0u;                                  // tokens 56..63 = 0
        pa3[3] = 0u;
    }
    // no barrier: P lives in registers; Phase C reads only VT (visible since wi2 sync)

    // ================ Phase C: O = P @ V -> half O into XS ====================
    {
        const unsigned vAddr4 = su + VT_OFF + (unsigned)(((h * 32 + lrow) * VTS + l8) * 2);
        float4 acc[4];
        #pragma unroll
        for (int nd = 0; nd < 4; nd++) acc[nd] = make_float4(0.f, 0.f, 0.f, 0.f);

        #pragma unroll
        for (int kss = 0; kss < 4; kss++) {
            unsigned b0, b1, b2, b3;
            #pragma unroll
            for (int n8 = 0; n8 < 2; n8++) {
                ldsm4(vAddr4 + n8 * (16 * VTS * 2) + kss * 32, b0, b1, b2, b3);
                mma16(acc[2 * n8],     pa0[kss], pa1[kss], pa2[kss], pa3[kss], b0, b1);
                mma16(acc[2 * n8 + 1], pa0[kss], pa1[kss], pa2[kss], pa3[kss], b2, b3);
            }
        }
        #pragma unroll
        for (int nd = 0; nd < 4; nd++) {
            int c0 = h * 32 + nd * 8 + t2;
            if (qr0 < 49) st2(xs + qr0 * RSH + c0, acc[nd].x, acc[nd].y);
            if (qr1 < 49) st2(xs + qr1 * RSH + c0, acc[nd].z, acc[nd].w);
        }
    }
    CPA_WAIT0();                  // proj weights resident in WT
    __syncthreads();              // O visible, all warps past WT consumption

    // ================ Phase D: out = O @ Wp^T + b =============================
    {
        float* og = out + (size_t)b * (49 * 128);
        float4 acc[4];
        #pragma unroll
        for (int a = 0; a < 4; a++) acc[a] = make_float4(0.f, 0.f, 0.f, 0.f);

        #pragma unroll
        for (int kss = 0; kss < 8; kss++) {
            unsigned a0, a1, a2, a3, b0, b1, b2, b3;
            ldsm4(xAddr + kss * 32, a0, a1, a2, a3);
            #pragma unroll
            for (int n8 = 0; n8 < 2; n8++) {
                ldsm4(wAddr4 + n8 * (16 * RSH * 2) + kss * 32, b0, b1, b2, b3);
                mma16(acc[2 * n8],     a0, a1, a2, a3, b0, b1);
                mma16(acc[2 * n8 + 1], a0, a1, a2, a3, b2, b3);
            }
        }
        #pragma unroll
        for (int n4 = 0; n4 < 4; n4++) {
            int d = nh * 32 + n4 * 8 + t2;
            float bx = __ldg(proj_b + d), by = __ldg(proj_b + d + 1);
            if (v0) {
                og[r0 * 128 + d]     = acc[n4].x + bx;
                og[r0 * 128 + d + 1] = acc[n4].y + by;
            }
            if (v1) {
                og[r1 * 128 + d]     = acc[n4].z + bx;
                og[r1 * 128 + d + 1] = acc[n4].w + by;
            }
        }
    }
}

extern "C" void kernel_launch(void* const* d_in, const int* in_sizes, int n_in,
                              void* d_out, int out_size)
{
    const float* x      = (const float*)d_in[0];
    const float* mask   = (const float*)d_in[1];
    const float* qkv_w  = (const float*)d_in[2];
    const float* qkv_b  = (const float*)d_in[3];
    const float* proj_w = (const float*)d_in[4];
    const float* proj_b = (const float*)d_in[5];
    const float* rpb    = (const float*)d_in[6];
    const int*   rpi    = (const int*)d_in[7];
    float* out = (float*)d_out;

    precompute_k<<<260, 256>>>(mask, qkv_w, proj_w, rpb, rpi);

    cudaFuncSetAttribute(winattn_h4,
                         cudaFuncAttributeMaxDynamicSharedMemorySize,
                         SMEM_BYTES);
    winattn_h4<<<16384, 512, SMEM_BYTES>>>(x, qkv_b, proj_b, out);
}